// round 14
// baseline (speedup 1.0000x reference)
#include <cuda_runtime.h>
#include <cuda_fp16.h>
#include <cstdint>
#include <math.h>

// Problem constants
#define TRI   32640      // 255 * 128, strict lower triangle count
#define NMAT  256
#define BATCH 1024
#define HIDW  1024
#define INW   256

// Device scratch (no allocations allowed)
// g_w2h: TILED layout — tile (by,kt) = 16 KB block of W2[by*128..+128, kt*64..+64]
//        in fp16, rows swizzled exactly as the GEMM2 smem stage expects.
// g_h  : same tiled layout, tiles (mx, kt), written by GEMM1's epilogue.
__device__ __half g_w2h[TRI * HIDW];
__device__ __half g_h  [BATCH * HIDW];
__device__ __half g_xh [BATCH * INW];   // x in fp16 (row-major)
__device__ __half g_w1h[HIDW * INW];    // W1 in fp16 (row-major)

// ---------------- helpers ----------------
__device__ __forceinline__ uint32_t smem_u32(const void* p){
    uint32_t a;
    asm("{ .reg .u64 t; cvta.to.shared.u64 t, %1; cvt.u32.u64 %0, t; }" : "=r"(a) : "l"(p));
    return a;
}
__device__ __forceinline__ void cp16(uint32_t s, const void* g){
    asm volatile("cp.async.cg.shared.global [%0], [%1], 16;" :: "r"(s), "l"(g) : "memory");
}
#define CP_COMMIT() asm volatile("cp.async.commit_group;" ::: "memory")
#define CP_WAIT1()  asm volatile("cp.async.wait_group 1;" ::: "memory")

__device__ __forceinline__ void mbar_init(uint32_t a, uint32_t cnt){
    asm volatile("mbarrier.init.shared.b64 [%0], %1;" :: "r"(a), "r"(cnt) : "memory");
}
__device__ __forceinline__ void mbar_expect(uint32_t a, uint32_t bytes){
    asm volatile("mbarrier.arrive.expect_tx.shared.b64 _, [%0], %1;" :: "r"(a), "r"(bytes) : "memory");
}
__device__ __forceinline__ void mbar_wait(uint32_t a, uint32_t parity){
    asm volatile(
        "{\n\t.reg .pred P;\n\t"
        "W%=:\n\t"
        "mbarrier.try_wait.parity.acquire.cta.shared::cta.b64 P, [%0], %1, 0x989680;\n\t"
        "@P bra.uni D%=;\n\t"
        "bra.uni W%=;\n\t"
        "D%=:\n\t}"
        :: "r"(a), "r"(parity) : "memory");
}
__device__ __forceinline__ void bulk_g2s(uint32_t dst, const void* src, uint32_t bytes, uint32_t mbar){
    asm volatile("cp.async.bulk.shared::cluster.global.mbarrier::complete_tx::bytes [%0], [%1], %2, [%3];"
                 :: "r"(dst), "l"(src), "r"(bytes), "r"(mbar) : "memory");
}

__device__ __forceinline__ uint4 lds128(uint32_t addr){
    uint4 v;
    asm volatile("ld.shared.v4.b32 {%0,%1,%2,%3}, [%4];"
                 : "=r"(v.x), "=r"(v.y), "=r"(v.z), "=r"(v.w) : "r"(addr));
    return v;
}
__device__ __forceinline__ uint32_t packh2(float a, float b){
    __half2 h = __floats2half2_rn(a, b);
    return *(uint32_t*)&h;
}
// fp16 MMA, fp32 accumulate. Logical k-order permuted (same perm on A and B).
__device__ __forceinline__ void mma16(float* d, uint32_t a0, uint32_t a1, uint32_t a2, uint32_t a3,
                                      uint32_t b0, uint32_t b1){
    asm volatile(
        "mma.sync.aligned.m16n8k16.row.col.f32.f16.f16.f32 "
        "{%0,%1,%2,%3}, {%4,%5,%6,%7}, {%8,%9}, {%0,%1,%2,%3};"
        : "+f"(d[0]), "+f"(d[1]), "+f"(d[2]), "+f"(d[3])
        : "r"(a0), "r"(a1), "r"(a2), "r"(a3), "r"(b0), "r"(b1));
}

// tile-internal swizzled offset (bytes): 128B rows, 1-bit chunk swizzle
__device__ __forceinline__ uint32_t g2_off(int row, int ch){
    return (uint32_t)(row * 128 + ((ch ^ ((row & 1) << 2)) << 4));
}

// ==================== FUSED: GEMM1 (bids 0..63) + conv_w2 (bids 64..16383) ====================
// gemm1: 128x128x32 fp16 mma pipeline, 8 warps 4Mx2N (identical to R13 gemm1).
// conv_w2: W2 fp32 -> fp16 tiled+swizzled, 16B chunks (identical math to R13).
// gemm1 blocks are first in the grid -> scheduled in wave 1; conv blocks
// (DRAM-bound) fill all remaining slots and overlap gemm1 (tensor-bound).
static constexpr int G1_STAGE = (128 + 128) * 32 * 2;          // 16 KB
static constexpr int G1_SMEM  = 3 * G1_STAGE;                  // 48 KB

__global__ void __launch_bounds__(256, 2)
fused_g1_convw2(const float* __restrict__ bias, const float* __restrict__ W2)
{
    if (blockIdx.x >= 64){
        // ---- conv_w2 branch ----
        int c = (blockIdx.x - 64) * 256 + threadIdx.x;   // < 4,177,920
        if (c < 255 * 16 * 128 * 8){
            int ch  = c & 7;
            int row = (c >> 3) & 127;
            int tk  = (c >> 10) & 15;
            int by  = c >> 14;
            const float4* src = (const float4*)(W2 + ((size_t)by * 128 + row) * 1024 + tk * 64 + ch * 8);
            float4 v0 = __ldg(src), v1 = __ldg(src + 1);
            uint4 o;
            o.x = packh2(v0.x, v0.y); o.y = packh2(v0.z, v0.w);
            o.z = packh2(v1.x, v1.y); o.w = packh2(v1.z, v1.w);
            char* dst = (char*)g_w2h + ((size_t)by * 16 + tk) * 16384;
            *(uint4*)(dst + g2_off(row, ch)) = o;
        }
        return;
    }

    // ---- gemm1 branch ----
    extern __shared__ char smem[];
    const uint32_t sbase = smem_u32(smem);
    const int tid  = threadIdx.x;
    const int lane = tid & 31;
    const int wid  = tid >> 5;
    const int wm   = wid & 3;
    const int wn   = wid >> 2;
    const int m0   = (blockIdx.x & 7) * 128;
    const int n0   = (blockIdx.x >> 3) * 128;
    const int t    = lane & 3;
    const int g    = lane >> 2;
    const int K    = INW;            // 256

    auto load_stage = [&](int stage, int kt){
        const uint32_t sa = sbase + stage * G1_STAGE;
        const uint32_t sb = sa + 128 * 32 * 2;
        const __half* Ag = g_xh  + (size_t)m0 * K + kt * 32;
        const __half* Bg = g_w1h + (size_t)n0 * K + kt * 32;
        #pragma unroll
        for (int it = 0; it < 2; it++){
            int idx = tid + it * 256;
            int row = idx >> 2, ch = idx & 3;
            uint32_t soff = (uint32_t)(row * 64 + ch * 16);
            cp16(sa + soff, Ag + (size_t)row * K + ch * 8);
            cp16(sb + soff, Bg + (size_t)row * K + ch * 8);
        }
    };

    float acc[2][8][4];
    #pragma unroll
    for (int mf = 0; mf < 2; mf++)
        #pragma unroll
        for (int nf = 0; nf < 8; nf++)
            #pragma unroll
            for (int q = 0; q < 4; q++) acc[mf][nf][q] = 0.0f;

    load_stage(0, 0); CP_COMMIT();
    load_stage(1, 1); CP_COMMIT();

    const int KT = K >> 5;
    for (int kt = 0; kt < KT; kt++){
        CP_WAIT1();
        __syncthreads();
        if (kt + 2 < KT) load_stage((kt + 2) % 3, kt + 2);
        CP_COMMIT();

        const uint32_t sa = sbase + (kt % 3) * G1_STAGE;
        const uint32_t sb = sa + 128 * 32 * 2;

        uint4 a_lo[2], a_hi[2];
        #pragma unroll
        for (int mf = 0; mf < 2; mf++){
            int r = wm * 32 + mf * 16 + g;
            a_lo[mf] = lds128(sa + (uint32_t)(r * 64 + t * 16));
            a_hi[mf] = lds128(sa + (uint32_t)((r + 8) * 64 + t * 16));
        }
        #pragma unroll
        for (int ng = 0; ng < 2; ng++){
            uint4 Bv[4];
            #pragma unroll
            for (int nf = 0; nf < 4; nf++){
                int n = wn * 64 + (ng * 4 + nf) * 8 + g;
                Bv[nf] = lds128(sb + (uint32_t)(n * 64 + t * 16));
            }
            #pragma unroll
            for (int mf = 0; mf < 2; mf++)
                #pragma unroll
                for (int nf = 0; nf < 4; nf++){
                    float* d = acc[mf][ng * 4 + nf];
                    mma16(d, a_lo[mf].x, a_hi[mf].x, a_lo[mf].y, a_hi[mf].y, Bv[nf].x, Bv[nf].y);
                    mma16(d, a_lo[mf].z, a_hi[mf].z, a_lo[mf].w, a_hi[mf].w, Bv[nf].z, Bv[nf].w);
                }
        }
    }

    // epilogue: softplus -> g_h in TILED+SWIZZLED layout (tile = (m0/128, e/64))
    #pragma unroll
    for (int mf = 0; mf < 2; mf++){
        const int rowL = wm * 32 + mf * 16 + g;        // local row in m-tile
        #pragma unroll
        for (int nf = 0; nf < 8; nf++){
            const int e0 = n0 + wn * 64 + nf * 8 + t * 2;
            const float bv0 = bias[e0], bv1 = bias[e0 + 1];
            float v0 = acc[mf][nf][0] + bv0, v1 = acc[mf][nf][1] + bv1;
            float v2 = acc[mf][nf][2] + bv0, v3 = acc[mf][nf][3] + bv1;
            v0 = fmaxf(v0, 0.0f) + log1pf(__expf(-fabsf(v0)));
            v1 = fmaxf(v1, 0.0f) + log1pf(__expf(-fabsf(v1)));
            v2 = fmaxf(v2, 0.0f) + log1pf(__expf(-fabsf(v2)));
            v3 = fmaxf(v3, 0.0f) + log1pf(__expf(-fabsf(v3)));
            const int tIdx = ((m0 >> 7) << 4) + (e0 >> 6);
            const int ch   = (e0 >> 3) & 7;
            char* tb = (char*)g_h + (size_t)tIdx * 16384 + (e0 & 7) * 2;
            *(__half2*)(tb + g2_off(rowL,     ch)) = __floats2half2_rn(v0, v1);
            *(__half2*)(tb + g2_off(rowL + 8, ch)) = __floats2half2_rn(v2, v3);
        }
    }
}

// ==================== GEMM2: 128x128x64, warp tile 32x64, 2 CTA/SM ====================
// Tiles arrive via cp.async.bulk (2 x 16KB per ktile, ONE issuing thread) from
// pre-swizzled tiled gmem -> zero LSU dispatch pressure. mbarrier-paced 3-stage
// pipeline; fragment-level LDS/MMA software pipelining.
static constexpr int G2_STAGE = 32768;                 // A(16KB) + B(16KB)
static constexpr int G2_SMEM  = 3 * G2_STAGE + 256;    // + mbarriers/align

__global__ void __launch_bounds__(256, 2)
gemm2_f16(const float* __restrict__ bias, float* __restrict__ O_)
{
    extern __shared__ char smem[];
    const uint32_t sb0  = (smem_u32(smem) + 127) & ~127u;   // stage buffers (128B aligned)
    const uint32_t mbar = sb0 + 3 * G2_STAGE;               // 3 mbarriers
    const int tid  = threadIdx.x;
    const int lane = tid & 31;
    const int wid  = tid >> 5;
    const int wm   = wid & 3;        // 4 warps along M (32 rows each)
    const int wn   = wid >> 2;       // 2 warps along N (64 cols each)
    const int m0   = blockIdx.x * 128;
    const int n0   = blockIdx.y * 128;
    const int t    = lane & 3;
    const int g    = lane >> 2;
    const int KT   = 16;             // K=1024, BK=64

    const __half* Atiles = g_h   + (size_t)(blockIdx.x * 16) * 8192;
    const __half* Btiles = g_w2h + (size_t)(blockIdx.y * 16) * 8192;

    if (tid == 0){
        mbar_init(mbar,      1);
        mbar_init(mbar + 8,  1);
        mbar_init(mbar + 16, 1);
    }
    __syncthreads();

    auto issue = [&](int T){
        uint32_t m = mbar + (T % 3) * 8;
        mbar_expect(m, 32768);
        bulk_g2s(sb0 + (T % 3) * G2_STAGE,         Atiles + (size_t)T * 8192, 16384, m);
        bulk_g2s(sb0 + (T % 3) * G2_STAGE + 16384, Btiles + (size_t)T * 8192, 16384, m);
    };
    if (tid == 0){ issue(0); issue(1); issue(2); }

    uint4 AL[2], AH[2], Bc[4], Bn[4];
    auto ldsA = [&](uint32_t sa, int ch){
        #pragma unroll
        for (int mf = 0; mf < 2; mf++){
            int r = wm * 32 + mf * 16 + g;
            AL[mf] = lds128(sa + g2_off(r,     ch));
            AH[mf] = lds128(sa + g2_off(r + 8, ch));
        }
    };
    auto ldsB = [&](uint4* Bv, uint32_t sbB, int ch, int ng){
        #pragma unroll
        for (int nf = 0; nf < 4; nf++){
            int n = wn * 64 + (ng * 4 + nf) * 8 + g;
            Bv[nf] = lds128(sbB + g2_off(n, ch));
        }
    };

    float acc[2][8][4];
    #pragma unroll
    for (int mf = 0; mf < 2; mf++)
        #pragma unroll
        for (int nf = 0; nf < 8; nf++)
            #pragma unroll
            for (int q = 0; q < 4; q++) acc[mf][nf][q] = 0.0f;

    auto mmag = [&](const uint4* Bv, int nf0){
        #pragma unroll
        for (int mf = 0; mf < 2; mf++)
            #pragma unroll
            for (int nf = 0; nf < 4; nf++){
                float* d = acc[mf][nf0 + nf];
                mma16(d, AL[mf].x, AH[mf].x, AL[mf].y, AH[mf].y, Bv[nf].x, Bv[nf].y);
                mma16(d, AL[mf].z, AH[mf].z, AL[mf].w, AH[mf].w, Bv[nf].z, Bv[nf].w);
            }
    };

    // prologue: stage 0 ready -> preload (kt=0, kk=0) fragments
    mbar_wait(mbar, 0);
    ldsA(sb0, t);
    ldsB(Bc, sb0 + 16384, t, 0);

    for (int kt = 0; kt < KT; kt++){
        if (kt + 1 < KT){
            int T = kt + 1;
            mbar_wait(mbar + (T % 3) * 8, (T / 3) & 1);
        }
        const uint32_t sa  = sb0 + (kt % 3) * G2_STAGE;
        const uint32_t sbB = sa + 16384;

        // g0: MMA(kk0,ng0); prefetch B(kk0,ng1)
        ldsB(Bn, sbB, t, 1);
        mmag(Bc, 0);
        // g1: MMA(kk0,ng1); prefetch B(kk1,ng0)
        ldsB(Bc, sbB, 4 + t, 0);
        mmag(Bn, 4);
        // g2: reload A(kk1); MMA(kk1,ng0); prefetch B(kk1,ng1)
        ldsA(sa, 4 + t);
        ldsB(Bn, sbB, 4 + t, 1);
        mmag(Bc, 0);
        // g3: MMA(kk1,ng1); cross-tile prefetch of (kt+1, kk0) fragments
        mmag(Bn, 4);
        if (kt + 1 < KT){
            const uint32_t sa2 = sb0 + ((kt + 1) % 3) * G2_STAGE;
            ldsA(sa2, t);
            ldsB(Bc, sa2 + 16384, t, 0);
        }

        __syncthreads();                 // stage kt%3 fully consumed by all warps
        if (kt + 3 < KT && tid == 0) issue(kt + 3);
    }

    // epilogue: scatter e -> (i,j) strict lower triangle (grid covers e < TRI exactly)
    #pragma unroll
    for (int mf = 0; mf < 2; mf++){
        const int rbase = m0 + wm * 32 + mf * 16 + g;
        #pragma unroll
        for (int nf = 0; nf < 8; nf++){
            const int e0 = n0 + wn * 64 + nf * 8 + t * 2;
            const float bv0 = bias[e0], bv1 = bias[e0 + 1];
            // e -> (i,j): i(i-1)/2 <= e < i(i+1)/2 ; j = e - i(i-1)/2
            int i = (int)((1.0f + sqrtf(8.0f * (float)e0 + 1.0f)) * 0.5f);
            while (i * (i - 1) / 2 > e0) i--;
            while ((i + 1) * i / 2 <= e0) i++;
            int j = e0 - i * (i - 1) / 2;
            int i1 = i, j1 = j + 1;
            if (j1 >= i1){ i1 = i + 1; j1 = 0; }
            float* o0 = O_ + (size_t)rbase * (NMAT * NMAT);
            float* o8 = o0 + (size_t)8 * (NMAT * NMAT);
            o0[i  * NMAT + j ] = acc[mf][nf][0] + bv0;
            o0[i1 * NMAT + j1] = acc[mf][nf][1] + bv1;
            o8[i  * NMAT + j ] = acc[mf][nf][2] + bv0;
            o8[i1 * NMAT + j1] = acc[mf][nf][3] + bv1;
        }
    }
}

// -------------------------------------------------------------------------
// x / W1 fp32 -> fp16 (row-major), single small launch (runs before fused).
// blocks [0,256): x ; [256,512): W1
// -------------------------------------------------------------------------
__global__ void __launch_bounds__(256) conv_xw1(const float4* __restrict__ x,
                                               const float4* __restrict__ W1)
{
    const int b = blockIdx.x;
    if (b < 256){
        int i = b * 256 + threadIdx.x;             // n4 = 65536
        float4 v = x[i];
        uint2 w;
        w.x = packh2(v.x, v.y);
        w.y = packh2(v.z, v.w);
        ((uint2*)g_xh)[i] = w;
    } else {
        int i = (b - 256) * 256 + threadIdx.x;     // n4 = 65536
        float4 v = W1[i];
        uint2 w;
        w.x = packh2(v.x, v.y);
        w.y = packh2(v.z, v.w);
        ((uint2*)g_w1h)[i] = w;
    }
}

// -------------------------------------------------------------------------
// Antisymmetrize, 64x64 tiles, float4 transfers, smem transpose.
// Diagonal tiles use a float4 fast path for quads strictly above the diagonal.
// -------------------------------------------------------------------------
__global__ void __launch_bounds__(256) antisym64(float* __restrict__ out)
{
    __shared__ float s[64][65];
    const int bt = blockIdx.x;
    const int pr = blockIdx.y;
    int ti = 0;
    while ((ti + 1) * (ti + 2) / 2 <= pr) ti++;
    const int tj = pr - ti * (ti + 1) / 2;
    const int tx = threadIdx.x & 15;     // float4 column index (16 per row)
    const int ty = threadIdx.x >> 4;     // row group (16 rows per pass)
    float* base = out + (size_t)bt * (NMAT * NMAT);

    // load 64x64 tile at (ti,tj), float4-coalesced
    #pragma unroll
    for (int it = 0; it < 4; it++){
        int r = ty + it * 16;
        float4 v = *(const float4*)(base + (size_t)(ti * 64 + r) * NMAT + tj * 64 + tx * 4);
        s[r][tx * 4 + 0] = v.x;
        s[r][tx * 4 + 1] = v.y;
        s[r][tx * 4 + 2] = v.z;
        s[r][tx * 4 + 3] = v.w;
    }
    __syncthreads();

    if (ti != tj){
        // write full transposed-negated tile at (tj,ti), float4-coalesced
        #pragma unroll
        for (int it = 0; it < 4; it++){
            int jj = ty + it * 16;
            float4 v;
            v.x = -s[tx * 4 + 0][jj];
            v.y = -s[tx * 4 + 1][jj];
            v.z = -s[tx * 4 + 2][jj];
            v.w = -s[tx * 4 + 3][jj];
            *(float4*)(base + (size_t)(tj * 64 + jj) * NMAT + ti * 64 + tx * 4) = v;
        }
    } else {
        // diagonal tile: upper-strict = -lower^T, diagonal = 0
        #pragma unroll
        for (int it = 0; it < 4; it++){
            int jj = ty + it * 16;
            float* orow = base + (size_t)(ti * 64 + jj) * NMAT + ti * 64;
            int ii0 = tx * 4;
            if (ii0 > jj){
                // whole quad strictly above diagonal: vector store
                float4 v;
                v.x = -s[ii0 + 0][jj];
                v.y = -s[ii0 + 1][jj];
                v.z = -s[ii0 + 2][jj];
                v.w = -s[ii0 + 3][jj];
                *(float4*)(orow + ii0) = v;
            } else if (ii0 + 3 >= jj){
                // straddles the diagonal: per-element
                #pragma unroll
                for (int k = 0; k < 4; k++){
                    int ii = ii0 + k;
                    if (ii > jj)       orow[ii] = -s[ii][jj];
                    else if (ii == jj) orow[ii] = 0.0f;
                }
            }
        }
    }
}

// -------------------------------------------------------------------------
extern "C" void kernel_launch(void* const* d_in, const int* in_sizes, int n_in,
                              void* d_out, int out_size)
{
    const float* x  = (const float*)d_in[0];   // [1024, 256]
    const float* W1 = (const float*)d_in[1];   // [1024, 256]
    const float* b1 = (const float*)d_in[2];   // [1024]
    const float* W2 = (const float*)d_in[3];   // [32896, 1024]
    const float* b2 = (const float*)d_in[4];   // [32896]
    float* out = (float*)d_out;                // [1024, 256, 256]

    cudaFuncSetAttribute(fused_g1_convw2, cudaFuncAttributeMaxDynamicSharedMemorySize, G1_SMEM);
    cudaFuncSetAttribute(gemm2_f16, cudaFuncAttributeMaxDynamicSharedMemorySize, G2_SMEM);

    // Small conversions first (gemm1's inputs)
    conv_xw1<<<512, 256>>>((const float4*)x, (const float4*)W1);

    // Fused: gemm1 (64 blocks, tensor-bound) + conv_w2 (16320 blocks, DRAM-bound)
    fused_g1_convw2<<<64 + 16320, 256, G1_SMEM>>>(b1, W2);

    // GEMM2: elements = h @ W2^T + b2 -> strict lower triangle of out
    //        (M=1024, N=TRI=255*128, K=1024), bulk-copy pipeline
    gemm2_f16<<<dim3(8, 255), 256, G2_SMEM>>>(b2, out);
    // Upper triangle = -lower^T, diagonal = 0 (64x64 float4 tiles)
    antisym64<<<dim3(1024, 10), 256>>>(out);
}

// round 15
// speedup vs baseline: 1.0759x; 1.0759x over previous
#include <cuda_runtime.h>
#include <cuda_fp16.h>
#include <cstdint>
#include <math.h>

// Problem constants
#define TRI   32640      // 255 * 128, strict lower triangle count
#define NMAT  256
#define BATCH 1024
#define HIDW  1024
#define INW   256

// Device scratch (no allocations allowed)
// g_w2h: TILED layout — tile (by,kt) = 16 KB block of W2[by*128..+128, kt*64..+64]
//        in fp16, rows swizzled exactly as the GEMM2 smem stage expects.
// g_h  : same tiled layout, tiles (mx, kt), written by GEMM1's epilogue.
__device__ __half g_w2h[TRI * HIDW];
__device__ __half g_h  [BATCH * HIDW];
__device__ __half g_xh [BATCH * INW];   // x in fp16 (row-major)
__device__ __half g_w1h[HIDW * INW];    // W1 in fp16 (row-major)

// ---------------- helpers ----------------
__device__ __forceinline__ uint32_t smem_u32(const void* p){
    uint32_t a;
    asm("{ .reg .u64 t; cvta.to.shared.u64 t, %1; cvt.u32.u64 %0, t; }" : "=r"(a) : "l"(p));
    return a;
}
__device__ __forceinline__ void cp16(uint32_t s, const void* g){
    asm volatile("cp.async.cg.shared.global [%0], [%1], 16;" :: "r"(s), "l"(g) : "memory");
}
#define CP_COMMIT() asm volatile("cp.async.commit_group;" ::: "memory")
#define CP_WAIT1()  asm volatile("cp.async.wait_group 1;" ::: "memory")

__device__ __forceinline__ void mbar_init(uint32_t a, uint32_t cnt){
    asm volatile("mbarrier.init.shared.b64 [%0], %1;" :: "r"(a), "r"(cnt) : "memory");
}
__device__ __forceinline__ void mbar_expect(uint32_t a, uint32_t bytes){
    asm volatile("mbarrier.arrive.expect_tx.shared.b64 _, [%0], %1;" :: "r"(a), "r"(bytes) : "memory");
}
__device__ __forceinline__ void mbar_wait(uint32_t a, uint32_t parity){
    asm volatile(
        "{\n\t.reg .pred P;\n\t"
        "W%=:\n\t"
        "mbarrier.try_wait.parity.acquire.cta.shared::cta.b64 P, [%0], %1, 0x989680;\n\t"
        "@P bra.uni D%=;\n\t"
        "bra.uni W%=;\n\t"
        "D%=:\n\t}"
        :: "r"(a), "r"(parity) : "memory");
}
__device__ __forceinline__ void bulk_g2s(uint32_t dst, const void* src, uint32_t bytes, uint32_t mbar){
    asm volatile("cp.async.bulk.shared::cluster.global.mbarrier::complete_tx::bytes [%0], [%1], %2, [%3];"
                 :: "r"(dst), "l"(src), "r"(bytes), "r"(mbar) : "memory");
}

__device__ __forceinline__ uint4 lds128(uint32_t addr){
    uint4 v;
    asm volatile("ld.shared.v4.b32 {%0,%1,%2,%3}, [%4];"
                 : "=r"(v.x), "=r"(v.y), "=r"(v.z), "=r"(v.w) : "r"(addr));
    return v;
}
__device__ __forceinline__ uint32_t packh2(float a, float b){
    __half2 h = __floats2half2_rn(a, b);
    return *(uint32_t*)&h;
}
// fp16 MMA, fp32 accumulate. Logical k-order permuted (same perm on A and B).
__device__ __forceinline__ void mma16(float* d, uint32_t a0, uint32_t a1, uint32_t a2, uint32_t a3,
                                      uint32_t b0, uint32_t b1){
    asm volatile(
        "mma.sync.aligned.m16n8k16.row.col.f32.f16.f16.f32 "
        "{%0,%1,%2,%3}, {%4,%5,%6,%7}, {%8,%9}, {%0,%1,%2,%3};"
        : "+f"(d[0]), "+f"(d[1]), "+f"(d[2]), "+f"(d[3])
        : "r"(a0), "r"(a1), "r"(a2), "r"(a3), "r"(b0), "r"(b1));
}

// tile-internal swizzled offset (bytes): 128B rows, 1-bit chunk swizzle
__device__ __forceinline__ uint32_t g2_off(int row, int ch){
    return (uint32_t)(row * 128 + ((ch ^ ((row & 1) << 2)) << 4));
}

// ==================== GEMM1: 128x128x32, 8 warps 4Mx2N, 2 CTA/SM ====================
static constexpr int G1_STAGE = (128 + 128) * 32 * 2;          // 16 KB
static constexpr int G1_SMEM  = 3 * G1_STAGE;                  // 48 KB

__global__ void __launch_bounds__(256, 2)
gemm1_f16(const float* __restrict__ bias)
{
    extern __shared__ char smem[];
    const uint32_t sbase = smem_u32(smem);
    const int tid  = threadIdx.x;
    const int lane = tid & 31;
    const int wid  = tid >> 5;
    const int wm   = wid & 3;
    const int wn   = wid >> 2;
    const int m0   = blockIdx.x * 128;
    const int n0   = blockIdx.y * 128;
    const int t    = lane & 3;
    const int g    = lane >> 2;
    const int K    = INW;            // 256

    auto load_stage = [&](int stage, int kt){
        const uint32_t sa = sbase + stage * G1_STAGE;
        const uint32_t sb = sa + 128 * 32 * 2;
        const __half* Ag = g_xh  + (size_t)m0 * K + kt * 32;
        const __half* Bg = g_w1h + (size_t)n0 * K + kt * 32;
        #pragma unroll
        for (int it = 0; it < 2; it++){
            int idx = tid + it * 256;
            int row = idx >> 2, ch = idx & 3;
            uint32_t soff = (uint32_t)(row * 64 + ch * 16);
            cp16(sa + soff, Ag + (size_t)row * K + ch * 8);
            cp16(sb + soff, Bg + (size_t)row * K + ch * 8);
        }
    };

    float acc[2][8][4];
    #pragma unroll
    for (int mf = 0; mf < 2; mf++)
        #pragma unroll
        for (int nf = 0; nf < 8; nf++)
            #pragma unroll
            for (int q = 0; q < 4; q++) acc[mf][nf][q] = 0.0f;

    load_stage(0, 0); CP_COMMIT();
    load_stage(1, 1); CP_COMMIT();

    const int KT = K >> 5;
    for (int kt = 0; kt < KT; kt++){
        CP_WAIT1();
        __syncthreads();
        if (kt + 2 < KT) load_stage((kt + 2) % 3, kt + 2);
        CP_COMMIT();

        const uint32_t sa = sbase + (kt % 3) * G1_STAGE;
        const uint32_t sb = sa + 128 * 32 * 2;

        uint4 a_lo[2], a_hi[2];
        #pragma unroll
        for (int mf = 0; mf < 2; mf++){
            int r = wm * 32 + mf * 16 + g;
            a_lo[mf] = lds128(sa + (uint32_t)(r * 64 + t * 16));
            a_hi[mf] = lds128(sa + (uint32_t)((r + 8) * 64 + t * 16));
        }
        #pragma unroll
        for (int ng = 0; ng < 2; ng++){
            uint4 Bv[4];
            #pragma unroll
            for (int nf = 0; nf < 4; nf++){
                int n = wn * 64 + (ng * 4 + nf) * 8 + g;
                Bv[nf] = lds128(sb + (uint32_t)(n * 64 + t * 16));
            }
            #pragma unroll
            for (int mf = 0; mf < 2; mf++)
                #pragma unroll
                for (int nf = 0; nf < 4; nf++){
                    float* d = acc[mf][ng * 4 + nf];
                    mma16(d, a_lo[mf].x, a_hi[mf].x, a_lo[mf].y, a_hi[mf].y, Bv[nf].x, Bv[nf].y);
                    mma16(d, a_lo[mf].z, a_hi[mf].z, a_lo[mf].w, a_hi[mf].w, Bv[nf].z, Bv[nf].w);
                }
        }
    }

    // epilogue: softplus -> g_h in TILED+SWIZZLED layout (tile = (m0/128, e/64))
    #pragma unroll
    for (int mf = 0; mf < 2; mf++){
        const int rowL = wm * 32 + mf * 16 + g;        // local row in m-tile
        #pragma unroll
        for (int nf = 0; nf < 8; nf++){
            const int e0 = n0 + wn * 64 + nf * 8 + t * 2;
            const float bv0 = bias[e0], bv1 = bias[e0 + 1];
            float v0 = acc[mf][nf][0] + bv0, v1 = acc[mf][nf][1] + bv1;
            float v2 = acc[mf][nf][2] + bv0, v3 = acc[mf][nf][3] + bv1;
            v0 = fmaxf(v0, 0.0f) + log1pf(__expf(-fabsf(v0)));
            v1 = fmaxf(v1, 0.0f) + log1pf(__expf(-fabsf(v1)));
            v2 = fmaxf(v2, 0.0f) + log1pf(__expf(-fabsf(v2)));
            v3 = fmaxf(v3, 0.0f) + log1pf(__expf(-fabsf(v3)));
            const int tIdx = ((m0 >> 7) << 4) + (e0 >> 6);
            const int ch   = (e0 >> 3) & 7;
            char* tb = (char*)g_h + (size_t)tIdx * 16384 + (e0 & 7) * 2;
            *(__half2*)(tb + g2_off(rowL,     ch)) = __floats2half2_rn(v0, v1);
            *(__half2*)(tb + g2_off(rowL + 8, ch)) = __floats2half2_rn(v2, v3);
        }
    }
}

// ==================== GEMM2: 128x128x64, warp tile 32x64, 2 CTA/SM ====================
// Tiles arrive via cp.async.bulk (2 x 16KB per ktile, ONE issuing thread) from
// pre-swizzled tiled gmem -> zero LSU dispatch pressure. mbarrier-paced 3-stage
// pipeline; fragment-level LDS/MMA software pipelining.
static constexpr int G2_STAGE = 32768;                 // A(16KB) + B(16KB)
static constexpr int G2_SMEM  = 3 * G2_STAGE + 256;    // + mbarriers/align

__global__ void __launch_bounds__(256, 2)
gemm2_f16(const float* __restrict__ bias, float* __restrict__ O_)
{
    extern __shared__ char smem[];
    const uint32_t sb0  = (smem_u32(smem) + 127) & ~127u;   // stage buffers (128B aligned)
    const uint32_t mbar = sb0 + 3 * G2_STAGE;               // 3 mbarriers
    const int tid  = threadIdx.x;
    const int lane = tid & 31;
    const int wid  = tid >> 5;
    const int wm   = wid & 3;        // 4 warps along M (32 rows each)
    const int wn   = wid >> 2;       // 2 warps along N (64 cols each)
    const int m0   = blockIdx.x * 128;
    const int n0   = blockIdx.y * 128;
    const int t    = lane & 3;
    const int g    = lane >> 2;
    const int KT   = 16;             // K=1024, BK=64

    const __half* Atiles = g_h   + (size_t)(blockIdx.x * 16) * 8192;
    const __half* Btiles = g_w2h + (size_t)(blockIdx.y * 16) * 8192;

    if (tid == 0){
        mbar_init(mbar,      1);
        mbar_init(mbar + 8,  1);
        mbar_init(mbar + 16, 1);
    }
    __syncthreads();

    auto issue = [&](int T){
        uint32_t m = mbar + (T % 3) * 8;
        mbar_expect(m, 32768);
        bulk_g2s(sb0 + (T % 3) * G2_STAGE,         Atiles + (size_t)T * 8192, 16384, m);
        bulk_g2s(sb0 + (T % 3) * G2_STAGE + 16384, Btiles + (size_t)T * 8192, 16384, m);
    };
    if (tid == 0){ issue(0); issue(1); issue(2); }

    uint4 AL[2], AH[2], Bc[4], Bn[4];
    auto ldsA = [&](uint32_t sa, int ch){
        #pragma unroll
        for (int mf = 0; mf < 2; mf++){
            int r = wm * 32 + mf * 16 + g;
            AL[mf] = lds128(sa + g2_off(r,     ch));
            AH[mf] = lds128(sa + g2_off(r + 8, ch));
        }
    };
    auto ldsB = [&](uint4* Bv, uint32_t sbB, int ch, int ng){
        #pragma unroll
        for (int nf = 0; nf < 4; nf++){
            int n = wn * 64 + (ng * 4 + nf) * 8 + g;
            Bv[nf] = lds128(sbB + g2_off(n, ch));
        }
    };

    float acc[2][8][4];
    #pragma unroll
    for (int mf = 0; mf < 2; mf++)
        #pragma unroll
        for (int nf = 0; nf < 8; nf++)
            #pragma unroll
            for (int q = 0; q < 4; q++) acc[mf][nf][q] = 0.0f;

    auto mmag = [&](const uint4* Bv, int nf0){
        #pragma unroll
        for (int mf = 0; mf < 2; mf++)
            #pragma unroll
            for (int nf = 0; nf < 4; nf++){
                float* d = acc[mf][nf0 + nf];
                mma16(d, AL[mf].x, AH[mf].x, AL[mf].y, AH[mf].y, Bv[nf].x, Bv[nf].y);
                mma16(d, AL[mf].z, AH[mf].z, AL[mf].w, AH[mf].w, Bv[nf].z, Bv[nf].w);
            }
    };

    // prologue: stage 0 ready -> preload (kt=0, kk=0) fragments
    mbar_wait(mbar, 0);
    ldsA(sb0, t);
    ldsB(Bc, sb0 + 16384, t, 0);

    for (int kt = 0; kt < KT; kt++){
        if (kt + 1 < KT){
            int T = kt + 1;
            mbar_wait(mbar + (T % 3) * 8, (T / 3) & 1);
        }
        const uint32_t sa  = sb0 + (kt % 3) * G2_STAGE;
        const uint32_t sbB = sa + 16384;

        // g0: MMA(kk0,ng0); prefetch B(kk0,ng1)
        ldsB(Bn, sbB, t, 1);
        mmag(Bc, 0);
        // g1: MMA(kk0,ng1); prefetch B(kk1,ng0)
        ldsB(Bc, sbB, 4 + t, 0);
        mmag(Bn, 4);
        // g2: reload A(kk1); MMA(kk1,ng0); prefetch B(kk1,ng1)
        ldsA(sa, 4 + t);
        ldsB(Bn, sbB, 4 + t, 1);
        mmag(Bc, 0);
        // g3: MMA(kk1,ng1); cross-tile prefetch of (kt+1, kk0) fragments
        mmag(Bn, 4);
        if (kt + 1 < KT){
            const uint32_t sa2 = sb0 + ((kt + 1) % 3) * G2_STAGE;
            ldsA(sa2, t);
            ldsB(Bc, sa2 + 16384, t, 0);
        }

        __syncthreads();                 // stage kt%3 fully consumed by all warps
        if (kt + 3 < KT && tid == 0) issue(kt + 3);
    }

    // epilogue: scatter e -> (i,j) strict lower triangle (grid covers e < TRI exactly)
    #pragma unroll
    for (int mf = 0; mf < 2; mf++){
        const int rbase = m0 + wm * 32 + mf * 16 + g;
        #pragma unroll
        for (int nf = 0; nf < 8; nf++){
            const int e0 = n0 + wn * 64 + nf * 8 + t * 2;
            const float bv0 = bias[e0], bv1 = bias[e0 + 1];
            // e -> (i,j): i(i-1)/2 <= e < i(i+1)/2 ; j = e - i(i-1)/2
            int i = (int)((1.0f + sqrtf(8.0f * (float)e0 + 1.0f)) * 0.5f);
            while (i * (i - 1) / 2 > e0) i--;
            while ((i + 1) * i / 2 <= e0) i++;
            int j = e0 - i * (i - 1) / 2;
            int i1 = i, j1 = j + 1;
            if (j1 >= i1){ i1 = i + 1; j1 = 0; }
            float* o0 = O_ + (size_t)rbase * (NMAT * NMAT);
            float* o8 = o0 + (size_t)8 * (NMAT * NMAT);
            o0[i  * NMAT + j ] = acc[mf][nf][0] + bv0;
            o0[i1 * NMAT + j1] = acc[mf][nf][1] + bv1;
            o8[i  * NMAT + j ] = acc[mf][nf][2] + bv0;
            o8[i1 * NMAT + j1] = acc[mf][nf][3] + bv1;
        }
    }
}

// -------------------------------------------------------------------------
// Fused conversion kernel (single launch, no dynamic smem):
//   blocks [0, 16320)        : W2 fp32 -> fp16 tiled+swizzled (16B chunks)
//   blocks [16320, 16576)    : x  fp32 -> fp16 row-major
//   blocks [16576, 16832)    : W1 fp32 -> fp16 row-major
// -------------------------------------------------------------------------
__global__ void __launch_bounds__(256) conv_all(const float* __restrict__ W2,
                                               const float4* __restrict__ x,
                                               const float4* __restrict__ W1)
{
    const int b = blockIdx.x;
    if (b < 16320){
        int c = b * 256 + threadIdx.x;         // < 4,177,920
        int ch  = c & 7;
        int row = (c >> 3) & 127;
        int tk  = (c >> 10) & 15;
        int by  = c >> 14;
        const float4* src = (const float4*)(W2 + ((size_t)by * 128 + row) * 1024 + tk * 64 + ch * 8);
        float4 v0 = __ldg(src), v1 = __ldg(src + 1);
        uint4 o;
        o.x = packh2(v0.x, v0.y); o.y = packh2(v0.z, v0.w);
        o.z = packh2(v1.x, v1.y); o.w = packh2(v1.z, v1.w);
        char* dst = (char*)g_w2h + ((size_t)by * 16 + tk) * 16384;
        *(uint4*)(dst + g2_off(row, ch)) = o;
    } else if (b < 16576){
        int i = (b - 16320) * 256 + threadIdx.x;   // n4 = 65536
        float4 v = x[i];
        uint2 w;
        w.x = packh2(v.x, v.y);
        w.y = packh2(v.z, v.w);
        ((uint2*)g_xh)[i] = w;
    } else {
        int i = (b - 16576) * 256 + threadIdx.x;   // n4 = 65536
        float4 v = W1[i];
        uint2 w;
        w.x = packh2(v.x, v.y);
        w.y = packh2(v.z, v.w);
        ((uint2*)g_w1h)[i] = w;
    }
}

// -------------------------------------------------------------------------
// Antisymmetrize, 64x64 tiles, float4 transfers, smem transpose.
// Diagonal tiles use a float4 fast path for quads strictly above the diagonal.
// -------------------------------------------------------------------------
__global__ void __launch_bounds__(256) antisym64(float* __restrict__ out)
{
    __shared__ float s[64][65];
    const int bt = blockIdx.x;
    const int pr = blockIdx.y;
    int ti = 0;
    while ((ti + 1) * (ti + 2) / 2 <= pr) ti++;
    const int tj = pr - ti * (ti + 1) / 2;
    const int tx = threadIdx.x & 15;     // float4 column index (16 per row)
    const int ty = threadIdx.x >> 4;     // row group (16 rows per pass)
    float* base = out + (size_t)bt * (NMAT * NMAT);

    // load 64x64 tile at (ti,tj), float4-coalesced
    #pragma unroll
    for (int it = 0; it < 4; it++){
        int r = ty + it * 16;
        float4 v = *(const float4*)(base + (size_t)(ti * 64 + r) * NMAT + tj * 64 + tx * 4);
        s[r][tx * 4 + 0] = v.x;
        s[r][tx * 4 + 1] = v.y;
        s[r][tx * 4 + 2] = v.z;
        s[r][tx * 4 + 3] = v.w;
    }
    __syncthreads();

    if (ti != tj){
        // write full transposed-negated tile at (tj,ti), float4-coalesced
        #pragma unroll
        for (int it = 0; it < 4; it++){
            int jj = ty + it * 16;
            float4 v;
            v.x = -s[tx * 4 + 0][jj];
            v.y = -s[tx * 4 + 1][jj];
            v.z = -s[tx * 4 + 2][jj];
            v.w = -s[tx * 4 + 3][jj];
            *(float4*)(base + (size_t)(tj * 64 + jj) * NMAT + ti * 64 + tx * 4) = v;
        }
    } else {
        // diagonal tile: upper-strict = -lower^T, diagonal = 0
        #pragma unroll
        for (int it = 0; it < 4; it++){
            int jj = ty + it * 16;
            float* orow = base + (size_t)(ti * 64 + jj) * NMAT + ti * 64;
            int ii0 = tx * 4;
            if (ii0 > jj){
                // whole quad strictly above diagonal: vector store
                float4 v;
                v.x = -s[ii0 + 0][jj];
                v.y = -s[ii0 + 1][jj];
                v.z = -s[ii0 + 2][jj];
                v.w = -s[ii0 + 3][jj];
                *(float4*)(orow + ii0) = v;
            } else if (ii0 + 3 >= jj){
                // straddles the diagonal: per-element
                #pragma unroll
                for (int k = 0; k < 4; k++){
                    int ii = ii0 + k;
                    if (ii > jj)       orow[ii] = -s[ii][jj];
                    else if (ii == jj) orow[ii] = 0.0f;
                }
            }
        }
    }
}

// -------------------------------------------------------------------------
extern "C" void kernel_launch(void* const* d_in, const int* in_sizes, int n_in,
                              void* d_out, int out_size)
{
    const float* x  = (const float*)d_in[0];   // [1024, 256]
    const float* W1 = (const float*)d_in[1];   // [1024, 256]
    const float* b1 = (const float*)d_in[2];   // [1024]
    const float* W2 = (const float*)d_in[3];   // [32896, 1024]
    const float* b2 = (const float*)d_in[4];   // [32896]
    float* out = (float*)d_out;                // [1024, 256, 256]

    cudaFuncSetAttribute(gemm1_f16, cudaFuncAttributeMaxDynamicSharedMemorySize, G1_SMEM);
    cudaFuncSetAttribute(gemm2_f16, cudaFuncAttributeMaxDynamicSharedMemorySize, G2_SMEM);

    // All conversions in ONE launch (W2 tiled+swizzled, x/W1 row-major)
    conv_all<<<16832, 256>>>(W2, (const float4*)x, (const float4*)W1);

    // GEMM1: h = softplus(x @ W1^T + b1) -> g_h (fp16, tiled)   (M=1024, N=1024, K=256)
    gemm1_f16<<<dim3(8, 8), 256, G1_SMEM>>>(b1);
    // GEMM2: elements = h @ W2^T + b2 -> strict lower triangle of out
    //        (M=1024, N=TRI=255*128, K=1024), bulk-copy pipeline
    gemm2_f16<<<dim3(8, 255), 256, G2_SMEM>>>(b2, out);
    // Upper triangle = -lower^T, diagonal = 0 (64x64 float4 tiles)
    antisym64<<<dim3(1024, 10), 256>>>(out);
}

// round 16
// speedup vs baseline: 1.1776x; 1.0945x over previous
#include <cuda_runtime.h>
#include <cuda_fp16.h>
#include <cstdint>
#include <math.h>

// Problem constants
#define TRI   32640      // 255 * 128, strict lower triangle count
#define NMAT  256
#define BATCH 1024
#define HIDW  1024
#define INW   256

// Device scratch (no allocations allowed)
// g_w2h: TILED layout — tile (by,kt) = 16 KB block of W2[by*128..+128, kt*64..+64]
//        in fp16, rows swizzled exactly as the GEMM2 smem stage expects.
// g_h  : same tiled layout, tiles (mx, kt), written by GEMM1's epilogue.
__device__ __half g_w2h[TRI * HIDW];
__device__ __half g_h  [BATCH * HIDW];
__device__ __half g_xh [BATCH * INW];   // x in fp16 (row-major)
__device__ __half g_w1h[HIDW * INW];    // W1 in fp16 (row-major)

// ---------------- helpers ----------------
__device__ __forceinline__ uint32_t smem_u32(const void* p){
    uint32_t a;
    asm("{ .reg .u64 t; cvta.to.shared.u64 t, %1; cvt.u32.u64 %0, t; }" : "=r"(a) : "l"(p));
    return a;
}
__device__ __forceinline__ void cp16(uint32_t s, const void* g){
    asm volatile("cp.async.cg.shared.global [%0], [%1], 16;" :: "r"(s), "l"(g) : "memory");
}
#define CP_COMMIT() asm volatile("cp.async.commit_group;" ::: "memory")
#define CP_WAIT1()  asm volatile("cp.async.wait_group 1;" ::: "memory")

__device__ __forceinline__ void mbar_init(uint32_t a, uint32_t cnt){
    asm volatile("mbarrier.init.shared.b64 [%0], %1;" :: "r"(a), "r"(cnt) : "memory");
}
__device__ __forceinline__ void mbar_expect(uint32_t a, uint32_t bytes){
    asm volatile("mbarrier.arrive.expect_tx.shared.b64 _, [%0], %1;" :: "r"(a), "r"(bytes) : "memory");
}
__device__ __forceinline__ void mbar_wait(uint32_t a, uint32_t parity){
    asm volatile(
        "{\n\t.reg .pred P;\n\t"
        "W%=:\n\t"
        "mbarrier.try_wait.parity.acquire.cta.shared::cta.b64 P, [%0], %1, 0x989680;\n\t"
        "@P bra.uni D%=;\n\t"
        "bra.uni W%=;\n\t"
        "D%=:\n\t}"
        :: "r"(a), "r"(parity) : "memory");
}
__device__ __forceinline__ void bulk_g2s(uint32_t dst, const void* src, uint32_t bytes, uint32_t mbar){
    asm volatile("cp.async.bulk.shared::cluster.global.mbarrier::complete_tx::bytes [%0], [%1], %2, [%3];"
                 :: "r"(dst), "l"(src), "r"(bytes), "r"(mbar) : "memory");
}

__device__ __forceinline__ uint4 lds128(uint32_t addr){
    uint4 v;
    asm volatile("ld.shared.v4.b32 {%0,%1,%2,%3}, [%4];"
                 : "=r"(v.x), "=r"(v.y), "=r"(v.z), "=r"(v.w) : "r"(addr));
    return v;
}
__device__ __forceinline__ uint32_t packh2(float a, float b){
    __half2 h = __floats2half2_rn(a, b);
    return *(uint32_t*)&h;
}
// fp16 MMA, fp32 accumulate. Logical k-order permuted (same perm on A and B).
__device__ __forceinline__ void mma16(float* d, uint32_t a0, uint32_t a1, uint32_t a2, uint32_t a3,
                                      uint32_t b0, uint32_t b1){
    asm volatile(
        "mma.sync.aligned.m16n8k16.row.col.f32.f16.f16.f32 "
        "{%0,%1,%2,%3}, {%4,%5,%6,%7}, {%8,%9}, {%0,%1,%2,%3};"
        : "+f"(d[0]), "+f"(d[1]), "+f"(d[2]), "+f"(d[3])
        : "r"(a0), "r"(a1), "r"(a2), "r"(a3), "r"(b0), "r"(b1));
}

// tile-internal swizzled offset (bytes): 128B rows, 1-bit chunk swizzle
__device__ __forceinline__ uint32_t g2_off(int row, int ch){
    return (uint32_t)(row * 128 + ((ch ^ ((row & 1) << 2)) << 4));
}

// ==================== GEMM1: 128x128x32, 8 warps 4Mx2N, 2 CTA/SM ====================
static constexpr int G1_STAGE = (128 + 128) * 32 * 2;          // 16 KB
static constexpr int G1_SMEM  = 3 * G1_STAGE;                  // 48 KB

__global__ void __launch_bounds__(256, 2)
gemm1_f16(const float* __restrict__ bias)
{
    extern __shared__ char smem[];
    const uint32_t sbase = smem_u32(smem);
    const int tid  = threadIdx.x;
    const int lane = tid & 31;
    const int wid  = tid >> 5;
    const int wm   = wid & 3;
    const int wn   = wid >> 2;
    const int m0   = blockIdx.x * 128;
    const int n0   = blockIdx.y * 128;
    const int t    = lane & 3;
    const int g    = lane >> 2;
    const int K    = INW;            // 256

    auto load_stage = [&](int stage, int kt){
        const uint32_t sa = sbase + stage * G1_STAGE;
        const uint32_t sb = sa + 128 * 32 * 2;
        const __half* Ag = g_xh  + (size_t)m0 * K + kt * 32;
        const __half* Bg = g_w1h + (size_t)n0 * K + kt * 32;
        #pragma unroll
        for (int it = 0; it < 2; it++){
            int idx = tid + it * 256;
            int row = idx >> 2, ch = idx & 3;
            uint32_t soff = (uint32_t)(row * 64 + ch * 16);
            cp16(sa + soff, Ag + (size_t)row * K + ch * 8);
            cp16(sb + soff, Bg + (size_t)row * K + ch * 8);
        }
    };

    float acc[2][8][4];
    #pragma unroll
    for (int mf = 0; mf < 2; mf++)
        #pragma unroll
        for (int nf = 0; nf < 8; nf++)
            #pragma unroll
            for (int q = 0; q < 4; q++) acc[mf][nf][q] = 0.0f;

    load_stage(0, 0); CP_COMMIT();
    load_stage(1, 1); CP_COMMIT();

    const int KT = K >> 5;
    for (int kt = 0; kt < KT; kt++){
        CP_WAIT1();
        __syncthreads();
        if (kt + 2 < KT) load_stage((kt + 2) % 3, kt + 2);
        CP_COMMIT();

        const uint32_t sa = sbase + (kt % 3) * G1_STAGE;
        const uint32_t sb = sa + 128 * 32 * 2;

        uint4 a_lo[2], a_hi[2];
        #pragma unroll
        for (int mf = 0; mf < 2; mf++){
            int r = wm * 32 + mf * 16 + g;
            a_lo[mf] = lds128(sa + (uint32_t)(r * 64 + t * 16));
            a_hi[mf] = lds128(sa + (uint32_t)((r + 8) * 64 + t * 16));
        }
        #pragma unroll
        for (int ng = 0; ng < 2; ng++){
            uint4 Bv[4];
            #pragma unroll
            for (int nf = 0; nf < 4; nf++){
                int n = wn * 64 + (ng * 4 + nf) * 8 + g;
                Bv[nf] = lds128(sb + (uint32_t)(n * 64 + t * 16));
            }
            #pragma unroll
            for (int mf = 0; mf < 2; mf++)
                #pragma unroll
                for (int nf = 0; nf < 4; nf++){
                    float* d = acc[mf][ng * 4 + nf];
                    mma16(d, a_lo[mf].x, a_hi[mf].x, a_lo[mf].y, a_hi[mf].y, Bv[nf].x, Bv[nf].y);
                    mma16(d, a_lo[mf].z, a_hi[mf].z, a_lo[mf].w, a_hi[mf].w, Bv[nf].z, Bv[nf].w);
                }
        }
    }

    // epilogue: softplus -> g_h in TILED+SWIZZLED layout (tile = (m0/128, e/64))
    #pragma unroll
    for (int mf = 0; mf < 2; mf++){
        const int rowL = wm * 32 + mf * 16 + g;        // local row in m-tile
        #pragma unroll
        for (int nf = 0; nf < 8; nf++){
            const int e0 = n0 + wn * 64 + nf * 8 + t * 2;
            const float bv0 = bias[e0], bv1 = bias[e0 + 1];
            float v0 = acc[mf][nf][0] + bv0, v1 = acc[mf][nf][1] + bv1;
            float v2 = acc[mf][nf][2] + bv0, v3 = acc[mf][nf][3] + bv1;
            v0 = fmaxf(v0, 0.0f) + log1pf(__expf(-fabsf(v0)));
            v1 = fmaxf(v1, 0.0f) + log1pf(__expf(-fabsf(v1)));
            v2 = fmaxf(v2, 0.0f) + log1pf(__expf(-fabsf(v2)));
            v3 = fmaxf(v3, 0.0f) + log1pf(__expf(-fabsf(v3)));
            const int tIdx = ((m0 >> 7) << 4) + (e0 >> 6);
            const int ch   = (e0 >> 3) & 7;
            char* tb = (char*)g_h + (size_t)tIdx * 16384 + (e0 & 7) * 2;
            *(__half2*)(tb + g2_off(rowL,     ch)) = __floats2half2_rn(v0, v1);
            *(__half2*)(tb + g2_off(rowL + 8, ch)) = __floats2half2_rn(v2, v3);
        }
    }
}

// ==================== GEMM2: 128x128x64, 4 warps 2Mx2N (warp tile 64x64), 2 CTA/SM ====================
// TMA bulk stages identical to R10 (A 16KB + B 16KB per ktile, pre-swizzled
// tiled gmem). Warp tile 64x64 halves per-byte smem redundancy (A x2, B x2):
// smem 1536 cyc < tensor 2048 cyc per SM-ktile-pair -> tensor-bound.
static constexpr int G2_STAGE = 32768;                 // A(16KB) + B(16KB)
static constexpr int G2_SMEM  = 3 * G2_STAGE + 256;    // + mbarriers/align

__global__ void __launch_bounds__(128, 2)
gemm2_f16(const float* __restrict__ bias, float* __restrict__ O_)
{
    extern __shared__ char smem[];
    const uint32_t sb0  = (smem_u32(smem) + 127) & ~127u;   // stage buffers (128B aligned)
    const uint32_t mbar = sb0 + 3 * G2_STAGE;               // 3 mbarriers
    const int tid  = threadIdx.x;
    const int lane = tid & 31;
    const int wid  = tid >> 5;       // 0..3
    const int wm   = wid & 1;        // 2 warps along M (64 rows each)
    const int wn   = wid >> 1;       // 2 warps along N (64 cols each)
    const int m0   = blockIdx.x * 128;
    const int n0   = blockIdx.y * 128;
    const int t    = lane & 3;
    const int g    = lane >> 2;
    const int KT   = 16;             // K=1024, BK=64

    const __half* Atiles = g_h   + (size_t)(blockIdx.x * 16) * 8192;
    const __half* Btiles = g_w2h + (size_t)(blockIdx.y * 16) * 8192;

    if (tid == 0){
        mbar_init(mbar,      1);
        mbar_init(mbar + 8,  1);
        mbar_init(mbar + 16, 1);
    }
    __syncthreads();

    auto issue = [&](int T){
        uint32_t m = mbar + (T % 3) * 8;
        mbar_expect(m, 32768);
        bulk_g2s(sb0 + (T % 3) * G2_STAGE,         Atiles + (size_t)T * 8192, 16384, m);
        bulk_g2s(sb0 + (T % 3) * G2_STAGE + 16384, Btiles + (size_t)T * 8192, 16384, m);
    };
    if (tid == 0){ issue(0); issue(1); issue(2); }

    uint4 AL[4], AH[4], Bc[4], Bn[4];
    auto ldsA = [&](uint32_t sa, int ch){
        #pragma unroll
        for (int mf = 0; mf < 4; mf++){
            int r = wm * 64 + mf * 16 + g;
            AL[mf] = lds128(sa + g2_off(r,     ch));
            AH[mf] = lds128(sa + g2_off(r + 8, ch));
        }
    };
    auto ldsB = [&](uint4* Bv, uint32_t sbB, int ch, int ng){
        #pragma unroll
        for (int nf = 0; nf < 4; nf++){
            int n = wn * 64 + (ng * 4 + nf) * 8 + g;
            Bv[nf] = lds128(sbB + g2_off(n, ch));
        }
    };

    float acc[4][8][4];
    #pragma unroll
    for (int mf = 0; mf < 4; mf++)
        #pragma unroll
        for (int nf = 0; nf < 8; nf++)
            #pragma unroll
            for (int q = 0; q < 4; q++) acc[mf][nf][q] = 0.0f;

    auto mmag = [&](const uint4* Bv, int nf0){
        #pragma unroll
        for (int mf = 0; mf < 4; mf++)
            #pragma unroll
            for (int nf = 0; nf < 4; nf++){
                float* d = acc[mf][nf0 + nf];
                mma16(d, AL[mf].x, AH[mf].x, AL[mf].y, AH[mf].y, Bv[nf].x, Bv[nf].y);
                mma16(d, AL[mf].z, AH[mf].z, AL[mf].w, AH[mf].w, Bv[nf].z, Bv[nf].w);
            }
    };

    // prologue: stage 0 ready -> preload (kt=0, kk=0) fragments
    mbar_wait(mbar, 0);
    ldsA(sb0, t);
    ldsB(Bc, sb0 + 16384, t, 0);

    for (int kt = 0; kt < KT; kt++){
        if (kt + 1 < KT){
            int T = kt + 1;
            mbar_wait(mbar + (T % 3) * 8, (T / 3) & 1);
        }
        const uint32_t sa  = sb0 + (kt % 3) * G2_STAGE;
        const uint32_t sbB = sa + 16384;

        // g0: MMA(kk0,ng0); prefetch B(kk0,ng1)
        ldsB(Bn, sbB, t, 1);
        mmag(Bc, 0);
        // g1: MMA(kk0,ng1); prefetch B(kk1,ng0)
        ldsB(Bc, sbB, 4 + t, 0);
        mmag(Bn, 4);
        // g2: reload A(kk1); MMA(kk1,ng0); prefetch B(kk1,ng1)
        ldsA(sa, 4 + t);
        ldsB(Bn, sbB, 4 + t, 1);
        mmag(Bc, 0);
        // g3: MMA(kk1,ng1); cross-tile prefetch of (kt+1, kk0) fragments
        mmag(Bn, 4);
        if (kt + 1 < KT){
            const uint32_t sa2 = sb0 + ((kt + 1) % 3) * G2_STAGE;
            ldsA(sa2, t);
            ldsB(Bc, sa2 + 16384, t, 0);
        }

        __syncthreads();                 // stage kt%3 fully consumed by all warps
        if (kt + 3 < KT && tid == 0) issue(kt + 3);
    }

    // epilogue: scatter e -> (i,j) strict lower triangle (grid covers e < TRI exactly)
    #pragma unroll
    for (int mf = 0; mf < 4; mf++){
        const int rbase = m0 + wm * 64 + mf * 16 + g;
        #pragma unroll
        for (int nf = 0; nf < 8; nf++){
            const int e0 = n0 + wn * 64 + nf * 8 + t * 2;
            const float bv0 = bias[e0], bv1 = bias[e0 + 1];
            // e -> (i,j): i(i-1)/2 <= e < i(i+1)/2 ; j = e - i(i-1)/2
            int i = (int)((1.0f + sqrtf(8.0f * (float)e0 + 1.0f)) * 0.5f);
            while (i * (i - 1) / 2 > e0) i--;
            while ((i + 1) * i / 2 <= e0) i++;
            int j = e0 - i * (i - 1) / 2;
            int i1 = i, j1 = j + 1;
            if (j1 >= i1){ i1 = i + 1; j1 = 0; }
            float* o0 = O_ + (size_t)rbase * (NMAT * NMAT);
            float* o8 = o0 + (size_t)8 * (NMAT * NMAT);
            o0[i  * NMAT + j ] = acc[mf][nf][0] + bv0;
            o0[i1 * NMAT + j1] = acc[mf][nf][1] + bv1;
            o8[i  * NMAT + j ] = acc[mf][nf][2] + bv0;
            o8[i1 * NMAT + j1] = acc[mf][nf][3] + bv1;
        }
    }
}

// -------------------------------------------------------------------------
// Fused conversion kernel (single launch, no dynamic smem):
//   blocks [0, 16320)        : W2 fp32 -> fp16 tiled+swizzled (16B chunks)
//   blocks [16320, 16576)    : x  fp32 -> fp16 row-major
//   blocks [16576, 16832)    : W1 fp32 -> fp16 row-major
// -------------------------------------------------------------------------
__global__ void __launch_bounds__(256) conv_all(const float* __restrict__ W2,
                                               const float4* __restrict__ x,
                                               const float4* __restrict__ W1)
{
    const int b = blockIdx.x;
    if (b < 16320){
        int c = b * 256 + threadIdx.x;         // < 4,177,920
        int ch  = c & 7;
        int row = (c >> 3) & 127;
        int tk  = (c >> 10) & 15;
        int by  = c >> 14;
        const float4* src = (const float4*)(W2 + ((size_t)by * 128 + row) * 1024 + tk * 64 + ch * 8);
        float4 v0 = __ldg(src), v1 = __ldg(src + 1);
        uint4 o;
        o.x = packh2(v0.x, v0.y); o.y = packh2(v0.z, v0.w);
        o.z = packh2(v1.x, v1.y); o.w = packh2(v1.z, v1.w);
        char* dst = (char*)g_w2h + ((size_t)by * 16 + tk) * 16384;
        *(uint4*)(dst + g2_off(row, ch)) = o;
    } else if (b < 16576){
        int i = (b - 16320) * 256 + threadIdx.x;   // n4 = 65536
        float4 v = x[i];
        uint2 w;
        w.x = packh2(v.x, v.y);
        w.y = packh2(v.z, v.w);
        ((uint2*)g_xh)[i] = w;
    } else {
        int i = (b - 16576) * 256 + threadIdx.x;   // n4 = 65536
        float4 v = W1[i];
        uint2 w;
        w.x = packh2(v.x, v.y);
        w.y = packh2(v.z, v.w);
        ((uint2*)g_w1h)[i] = w;
    }
}

// -------------------------------------------------------------------------
// Antisymmetrize, 64x64 tiles, float4 transfers, smem transpose.
// Diagonal tiles: load only lower-half quads, float4 fast path on stores.
// -------------------------------------------------------------------------
__global__ void __launch_bounds__(256) antisym64(float* __restrict__ out)
{
    __shared__ float s[64][65];
    const int bt = blockIdx.x;
    const int pr = blockIdx.y;
    int ti = 0;
    while ((ti + 1) * (ti + 2) / 2 <= pr) ti++;
    const int tj = pr - ti * (ti + 1) / 2;
    const int tx = threadIdx.x & 15;     // float4 column index (16 per row)
    const int ty = threadIdx.x >> 4;     // row group (16 rows per pass)
    float* base = out + (size_t)bt * (NMAT * NMAT);
    const bool diag = (ti == tj);

    // load 64x64 tile at (ti,tj), float4-coalesced.
    // Diagonal tiles only need s[ii][jj] for ii > jj: skip quads entirely
    // above the diagonal (tx*4 > r means cols > row -> unused).
    #pragma unroll
    for (int it = 0; it < 4; it++){
        int r = ty + it * 16;
        if (diag && tx * 4 > r) continue;
        float4 v = *(const float4*)(base + (size_t)(ti * 64 + r) * NMAT + tj * 64 + tx * 4);
        s[r][tx * 4 + 0] = v.x;
        s[r][tx * 4 + 1] = v.y;
        s[r][tx * 4 + 2] = v.z;
        s[r][tx * 4 + 3] = v.w;
    }
    __syncthreads();

    if (!diag){
        // write full transposed-negated tile at (tj,ti), float4-coalesced
        #pragma unroll
        for (int it = 0; it < 4; it++){
            int jj = ty + it * 16;
            float4 v;
            v.x = -s[tx * 4 + 0][jj];
            v.y = -s[tx * 4 + 1][jj];
            v.z = -s[tx * 4 + 2][jj];
            v.w = -s[tx * 4 + 3][jj];
            *(float4*)(base + (size_t)(tj * 64 + jj) * NMAT + ti * 64 + tx * 4) = v;
        }
    } else {
        // diagonal tile: upper-strict = -lower^T, diagonal = 0
        #pragma unroll
        for (int it = 0; it < 4; it++){
            int jj = ty + it * 16;
            float* orow = base + (size_t)(ti * 64 + jj) * NMAT + ti * 64;
            int ii0 = tx * 4;
            if (ii0 > jj){
                // whole quad strictly above diagonal: vector store
                float4 v;
                v.x = -s[ii0 + 0][jj];
                v.y = -s[ii0 + 1][jj];
                v.z = -s[ii0 + 2][jj];
                v.w = -s[ii0 + 3][jj];
                *(float4*)(orow + ii0) = v;
            } else if (ii0 + 3 >= jj){
                // straddles the diagonal: per-element
                #pragma unroll
                for (int k = 0; k < 4; k++){
                    int ii = ii0 + k;
                    if (ii > jj)       orow[ii] = -s[ii][jj];
                    else if (ii == jj) orow[ii] = 0.0f;
                }
            }
        }
    }
}

// -------------------------------------------------------------------------
extern "C" void kernel_launch(void* const* d_in, const int* in_sizes, int n_in,
                              void* d_out, int out_size)
{
    const float* x  = (const float*)d_in[0];   // [1024, 256]
    const float* W1 = (const float*)d_in[1];   // [1024, 256]
    const float* b1 = (const float*)d_in[2];   // [1024]
    const float* W2 = (const float*)d_in[3];   // [32896, 1024]
    const float* b2 = (const float*)d_in[4];   // [32896]
    float* out = (float*)d_out;                // [1024, 256, 256]

    cudaFuncSetAttribute(gemm1_f16, cudaFuncAttributeMaxDynamicSharedMemorySize, G1_SMEM);
    cudaFuncSetAttribute(gemm2_f16, cudaFuncAttributeMaxDynamicSharedMemorySize, G2_SMEM);

    // All conversions in ONE launch (W2 tiled+swizzled, x/W1 row-major)
    conv_all<<<16832, 256>>>(W2, (const float4*)x, (const float4*)W1);

    // GEMM1: h = softplus(x @ W1^T + b1) -> g_h (fp16, tiled)   (M=1024, N=1024, K=256)
    gemm1_f16<<<dim3(8, 8), 256, G1_SMEM>>>(b1);
    // GEMM2: elements = h @ W2^T + b2 -> strict lower triangle of out
    //        (M=1024, N=TRI=255*128, K=1024), bulk-copy pipeline, 64x64 warp tiles
    gemm2_f16<<<dim3(8, 255), 128, G2_SMEM>>>(b2, out);
    // Upper triangle = -lower^T, diagonal = 0 (64x64 float4 tiles)
    antisym64<<<dim3(1024, 10), 256>>>(out);
}

// round 17
// speedup vs baseline: 1.1841x; 1.0055x over previous
#include <cuda_runtime.h>
#include <cuda_fp16.h>
#include <cstdint>
#include <math.h>

// Problem constants
#define TRI   32640      // 255 * 128, strict lower triangle count
#define NMAT  256
#define BATCH 1024
#define HIDW  1024
#define INW   256

// Device scratch (no allocations allowed)
// g_w2h: TILED layout — tile (by,kt) = 16 KB block of W2[by*128..+128, kt*64..+64]
//        in fp16, rows swizzled exactly as the GEMM2 smem stage expects.
// g_h  : same tiled layout, tiles (mx, kt), written by GEMM1's epilogue.
__device__ __half g_w2h[TRI * HIDW];
__device__ __half g_h  [BATCH * HIDW];
__device__ __half g_xh [BATCH * INW];   // x in fp16 (row-major)
__device__ __half g_w1h[HIDW * INW];    // W1 in fp16 (row-major)

// ---------------- helpers ----------------
__device__ __forceinline__ uint32_t smem_u32(const void* p){
    uint32_t a;
    asm("{ .reg .u64 t; cvta.to.shared.u64 t, %1; cvt.u32.u64 %0, t; }" : "=r"(a) : "l"(p));
    return a;
}
__device__ __forceinline__ void cp16(uint32_t s, const void* g){
    asm volatile("cp.async.cg.shared.global [%0], [%1], 16;" :: "r"(s), "l"(g) : "memory");
}
#define CP_COMMIT() asm volatile("cp.async.commit_group;" ::: "memory")
#define CP_WAIT1()  asm volatile("cp.async.wait_group 1;" ::: "memory")

__device__ __forceinline__ void mbar_init(uint32_t a, uint32_t cnt){
    asm volatile("mbarrier.init.shared.b64 [%0], %1;" :: "r"(a), "r"(cnt) : "memory");
}
__device__ __forceinline__ void mbar_expect(uint32_t a, uint32_t bytes){
    asm volatile("mbarrier.arrive.expect_tx.shared.b64 _, [%0], %1;" :: "r"(a), "r"(bytes) : "memory");
}
__device__ __forceinline__ void mbar_wait(uint32_t a, uint32_t parity){
    asm volatile(
        "{\n\t.reg .pred P;\n\t"
        "W%=:\n\t"
        "mbarrier.try_wait.parity.acquire.cta.shared::cta.b64 P, [%0], %1, 0x989680;\n\t"
        "@P bra.uni D%=;\n\t"
        "bra.uni W%=;\n\t"
        "D%=:\n\t}"
        :: "r"(a), "r"(parity) : "memory");
}
__device__ __forceinline__ void bulk_g2s(uint32_t dst, const void* src, uint32_t bytes, uint32_t mbar){
    asm volatile("cp.async.bulk.shared::cluster.global.mbarrier::complete_tx::bytes [%0], [%1], %2, [%3];"
                 :: "r"(dst), "l"(src), "r"(bytes), "r"(mbar) : "memory");
}

__device__ __forceinline__ uint4 lds128(uint32_t addr){
    uint4 v;
    asm volatile("ld.shared.v4.b32 {%0,%1,%2,%3}, [%4];"
                 : "=r"(v.x), "=r"(v.y), "=r"(v.z), "=r"(v.w) : "r"(addr));
    return v;
}
__device__ __forceinline__ uint32_t packh2(float a, float b){
    __half2 h = __floats2half2_rn(a, b);
    return *(uint32_t*)&h;
}
// fp16 MMA, fp32 accumulate. Logical k-order permuted (same perm on A and B).
__device__ __forceinline__ void mma16(float* d, uint32_t a0, uint32_t a1, uint32_t a2, uint32_t a3,
                                      uint32_t b0, uint32_t b1){
    asm volatile(
        "mma.sync.aligned.m16n8k16.row.col.f32.f16.f16.f32 "
        "{%0,%1,%2,%3}, {%4,%5,%6,%7}, {%8,%9}, {%0,%1,%2,%3};"
        : "+f"(d[0]), "+f"(d[1]), "+f"(d[2]), "+f"(d[3])
        : "r"(a0), "r"(a1), "r"(a2), "r"(a3), "r"(b0), "r"(b1));
}

// tile-internal swizzled offset (bytes): 128B rows, 1-bit chunk swizzle
__device__ __forceinline__ uint32_t g2_off(int row, int ch){
    return (uint32_t)(row * 128 + ((ch ^ ((row & 1) << 2)) << 4));
}

// ==================== GEMM1: 128x128x32, 8 warps 4Mx2N, 2 CTA/SM ====================
static constexpr int G1_STAGE = (128 + 128) * 32 * 2;          // 16 KB
static constexpr int G1_SMEM  = 3 * G1_STAGE;                  // 48 KB

__global__ void __launch_bounds__(256, 2)
gemm1_f16(const float* __restrict__ bias)
{
    extern __shared__ char smem[];
    const uint32_t sbase = smem_u32(smem);
    const int tid  = threadIdx.x;
    const int lane = tid & 31;
    const int wid  = tid >> 5;
    const int wm   = wid & 3;
    const int wn   = wid >> 2;
    const int m0   = blockIdx.x * 128;
    const int n0   = blockIdx.y * 128;
    const int t    = lane & 3;
    const int g    = lane >> 2;
    const int K    = INW;            // 256

    auto load_stage = [&](int stage, int kt){
        const uint32_t sa = sbase + stage * G1_STAGE;
        const uint32_t sb = sa + 128 * 32 * 2;
        const __half* Ag = g_xh  + (size_t)m0 * K + kt * 32;
        const __half* Bg = g_w1h + (size_t)n0 * K + kt * 32;
        #pragma unroll
        for (int it = 0; it < 2; it++){
            int idx = tid + it * 256;
            int row = idx >> 2, ch = idx & 3;
            uint32_t soff = (uint32_t)(row * 64 + ch * 16);
            cp16(sa + soff, Ag + (size_t)row * K + ch * 8);
            cp16(sb + soff, Bg + (size_t)row * K + ch * 8);
        }
    };

    float acc[2][8][4];
    #pragma unroll
    for (int mf = 0; mf < 2; mf++)
        #pragma unroll
        for (int nf = 0; nf < 8; nf++)
            #pragma unroll
            for (int q = 0; q < 4; q++) acc[mf][nf][q] = 0.0f;

    load_stage(0, 0); CP_COMMIT();
    load_stage(1, 1); CP_COMMIT();

    const int KT = K >> 5;
    for (int kt = 0; kt < KT; kt++){
        CP_WAIT1();
        __syncthreads();
        if (kt + 2 < KT) load_stage((kt + 2) % 3, kt + 2);
        CP_COMMIT();

        const uint32_t sa = sbase + (kt % 3) * G1_STAGE;
        const uint32_t sb = sa + 128 * 32 * 2;

        uint4 a_lo[2], a_hi[2];
        #pragma unroll
        for (int mf = 0; mf < 2; mf++){
            int r = wm * 32 + mf * 16 + g;
            a_lo[mf] = lds128(sa + (uint32_t)(r * 64 + t * 16));
            a_hi[mf] = lds128(sa + (uint32_t)((r + 8) * 64 + t * 16));
        }
        #pragma unroll
        for (int ng = 0; ng < 2; ng++){
            uint4 Bv[4];
            #pragma unroll
            for (int nf = 0; nf < 4; nf++){
                int n = wn * 64 + (ng * 4 + nf) * 8 + g;
                Bv[nf] = lds128(sb + (uint32_t)(n * 64 + t * 16));
            }
            #pragma unroll
            for (int mf = 0; mf < 2; mf++)
                #pragma unroll
                for (int nf = 0; nf < 4; nf++){
                    float* d = acc[mf][ng * 4 + nf];
                    mma16(d, a_lo[mf].x, a_hi[mf].x, a_lo[mf].y, a_hi[mf].y, Bv[nf].x, Bv[nf].y);
                    mma16(d, a_lo[mf].z, a_hi[mf].z, a_lo[mf].w, a_hi[mf].w, Bv[nf].z, Bv[nf].w);
                }
        }
    }

    // epilogue: softplus -> g_h in TILED+SWIZZLED layout (tile = (m0/128, e/64))
    #pragma unroll
    for (int mf = 0; mf < 2; mf++){
        const int rowL = wm * 32 + mf * 16 + g;        // local row in m-tile
        #pragma unroll
        for (int nf = 0; nf < 8; nf++){
            const int e0 = n0 + wn * 64 + nf * 8 + t * 2;
            const float bv0 = bias[e0], bv1 = bias[e0 + 1];
            float v0 = acc[mf][nf][0] + bv0, v1 = acc[mf][nf][1] + bv1;
            float v2 = acc[mf][nf][2] + bv0, v3 = acc[mf][nf][3] + bv1;
            v0 = fmaxf(v0, 0.0f) + log1pf(__expf(-fabsf(v0)));
            v1 = fmaxf(v1, 0.0f) + log1pf(__expf(-fabsf(v1)));
            v2 = fmaxf(v2, 0.0f) + log1pf(__expf(-fabsf(v2)));
            v3 = fmaxf(v3, 0.0f) + log1pf(__expf(-fabsf(v3)));
            const int tIdx = ((m0 >> 7) << 4) + (e0 >> 6);
            const int ch   = (e0 >> 3) & 7;
            char* tb = (char*)g_h + (size_t)tIdx * 16384 + (e0 & 7) * 2;
            *(__half2*)(tb + g2_off(rowL,     ch)) = __floats2half2_rn(v0, v1);
            *(__half2*)(tb + g2_off(rowL + 8, ch)) = __floats2half2_rn(v2, v3);
        }
    }
}

// ==================== GEMM2: 128x128x64, 4 warps 2Mx2N (warp tile 64x64), 2 CTA/SM ====================
// TMA bulk stages (A 16KB + B 16KB per ktile, pre-swizzled tiled gmem).
// MMA groups split into two passes: 16 independent k-half0 MMAs first, then
// the 16 dependent k-half1 MMAs -> RAW distance 16 instrs, HMMA latency hidden.
static constexpr int G2_STAGE = 32768;                 // A(16KB) + B(16KB)
static constexpr int G2_SMEM  = 3 * G2_STAGE + 256;    // + mbarriers/align

__global__ void __launch_bounds__(128, 2)
gemm2_f16(const float* __restrict__ bias, float* __restrict__ O_)
{
    extern __shared__ char smem[];
    const uint32_t sb0  = (smem_u32(smem) + 127) & ~127u;   // stage buffers (128B aligned)
    const uint32_t mbar = sb0 + 3 * G2_STAGE;               // 3 mbarriers
    const int tid  = threadIdx.x;
    const int lane = tid & 31;
    const int wid  = tid >> 5;       // 0..3
    const int wm   = wid & 1;        // 2 warps along M (64 rows each)
    const int wn   = wid >> 1;       // 2 warps along N (64 cols each)
    const int m0   = blockIdx.x * 128;
    const int n0   = blockIdx.y * 128;
    const int t    = lane & 3;
    const int g    = lane >> 2;
    const int KT   = 16;             // K=1024, BK=64

    const __half* Atiles = g_h   + (size_t)(blockIdx.x * 16) * 8192;
    const __half* Btiles = g_w2h + (size_t)(blockIdx.y * 16) * 8192;

    if (tid == 0){
        mbar_init(mbar,      1);
        mbar_init(mbar + 8,  1);
        mbar_init(mbar + 16, 1);
    }
    __syncthreads();

    auto issue = [&](int T){
        uint32_t m = mbar + (T % 3) * 8;
        mbar_expect(m, 32768);
        bulk_g2s(sb0 + (T % 3) * G2_STAGE,         Atiles + (size_t)T * 8192, 16384, m);
        bulk_g2s(sb0 + (T % 3) * G2_STAGE + 16384, Btiles + (size_t)T * 8192, 16384, m);
    };
    if (tid == 0){ issue(0); issue(1); issue(2); }

    uint4 AL[4], AH[4], Bc[4], Bn[4];
    auto ldsA = [&](uint32_t sa, int ch){
        #pragma unroll
        for (int mf = 0; mf < 4; mf++){
            int r = wm * 64 + mf * 16 + g;
            AL[mf] = lds128(sa + g2_off(r,     ch));
            AH[mf] = lds128(sa + g2_off(r + 8, ch));
        }
    };
    auto ldsB = [&](uint4* Bv, uint32_t sbB, int ch, int ng){
        #pragma unroll
        for (int nf = 0; nf < 4; nf++){
            int n = wn * 64 + (ng * 4 + nf) * 8 + g;
            Bv[nf] = lds128(sbB + g2_off(n, ch));
        }
    };

    float acc[4][8][4];
    #pragma unroll
    for (int mf = 0; mf < 4; mf++)
        #pragma unroll
        for (int nf = 0; nf < 8; nf++)
            #pragma unroll
            for (int q = 0; q < 4; q++) acc[mf][nf][q] = 0.0f;

    // Two-pass MMA group: pass 1 = 16 independent MMAs (k-half0, distinct
    // accumulators), pass 2 = 16 k-half1 MMAs each 16 issues after its
    // producer. Same per-accumulator order (half0 then half1) as before.
    auto mmag = [&](const uint4* Bv, int nf0){
        #pragma unroll
        for (int mf = 0; mf < 4; mf++)
            #pragma unroll
            for (int nf = 0; nf < 4; nf++)
                mma16(acc[mf][nf0 + nf], AL[mf].x, AH[mf].x, AL[mf].y, AH[mf].y,
                      Bv[nf].x, Bv[nf].y);
        #pragma unroll
        for (int mf = 0; mf < 4; mf++)
            #pragma unroll
            for (int nf = 0; nf < 4; nf++)
                mma16(acc[mf][nf0 + nf], AL[mf].z, AH[mf].z, AL[mf].w, AH[mf].w,
                      Bv[nf].z, Bv[nf].w);
    };

    // prologue: stage 0 ready -> preload (kt=0, kk=0) fragments
    mbar_wait(mbar, 0);
    ldsA(sb0, t);
    ldsB(Bc, sb0 + 16384, t, 0);

    for (int kt = 0; kt < KT; kt++){
        if (kt + 1 < KT){
            int T = kt + 1;
            mbar_wait(mbar + (T % 3) * 8, (T / 3) & 1);
        }
        const uint32_t sa  = sb0 + (kt % 3) * G2_STAGE;
        const uint32_t sbB = sa + 16384;

        // g0: MMA(kk0,ng0); prefetch B(kk0,ng1)
        ldsB(Bn, sbB, t, 1);
        mmag(Bc, 0);
        // g1: MMA(kk0,ng1); prefetch B(kk1,ng0)
        ldsB(Bc, sbB, 4 + t, 0);
        mmag(Bn, 4);
        // g2: reload A(kk1); MMA(kk1,ng0); prefetch B(kk1,ng1)
        ldsA(sa, 4 + t);
        ldsB(Bn, sbB, 4 + t, 1);
        mmag(Bc, 0);
        // g3: MMA(kk1,ng1); cross-tile prefetch of (kt+1, kk0) fragments
        mmag(Bn, 4);
        if (kt + 1 < KT){
            const uint32_t sa2 = sb0 + ((kt + 1) % 3) * G2_STAGE;
            ldsA(sa2, t);
            ldsB(Bc, sa2 + 16384, t, 0);
        }

        __syncthreads();                 // stage kt%3 fully consumed by all warps
        if (kt + 3 < KT && tid == 0) issue(kt + 3);
    }

    // epilogue: scatter e -> (i,j) strict lower triangle (grid covers e < TRI exactly)
    #pragma unroll
    for (int mf = 0; mf < 4; mf++){
        const int rbase = m0 + wm * 64 + mf * 16 + g;
        #pragma unroll
        for (int nf = 0; nf < 8; nf++){
            const int e0 = n0 + wn * 64 + nf * 8 + t * 2;
            const float bv0 = bias[e0], bv1 = bias[e0 + 1];
            // e -> (i,j): i(i-1)/2 <= e < i(i+1)/2 ; j = e - i(i-1)/2
            int i = (int)((1.0f + sqrtf(8.0f * (float)e0 + 1.0f)) * 0.5f);
            while (i * (i - 1) / 2 > e0) i--;
            while ((i + 1) * i / 2 <= e0) i++;
            int j = e0 - i * (i - 1) / 2;
            int i1 = i, j1 = j + 1;
            if (j1 >= i1){ i1 = i + 1; j1 = 0; }
            float* o0 = O_ + (size_t)rbase * (NMAT * NMAT);
            float* o8 = o0 + (size_t)8 * (NMAT * NMAT);
            o0[i  * NMAT + j ] = acc[mf][nf][0] + bv0;
            o0[i1 * NMAT + j1] = acc[mf][nf][1] + bv1;
            o8[i  * NMAT + j ] = acc[mf][nf][2] + bv0;
            o8[i1 * NMAT + j1] = acc[mf][nf][3] + bv1;
        }
    }
}

// -------------------------------------------------------------------------
// Fused conversion kernel (single launch, no dynamic smem):
//   blocks [0, 16320)        : W2 fp32 -> fp16 tiled+swizzled (16B chunks)
//   blocks [16320, 16576)    : x  fp32 -> fp16 row-major
//   blocks [16576, 16832)    : W1 fp32 -> fp16 row-major
// -------------------------------------------------------------------------
__global__ void __launch_bounds__(256) conv_all(const float* __restrict__ W2,
                                               const float4* __restrict__ x,
                                               const float4* __restrict__ W1)
{
    const int b = blockIdx.x;
    if (b < 16320){
        int c = b * 256 + threadIdx.x;         // < 4,177,920
        int ch  = c & 7;
        int row = (c >> 3) & 127;
        int tk  = (c >> 10) & 15;
        int by  = c >> 14;
        const float4* src = (const float4*)(W2 + ((size_t)by * 128 + row) * 1024 + tk * 64 + ch * 8);
        float4 v0 = __ldg(src), v1 = __ldg(src + 1);
        uint4 o;
        o.x = packh2(v0.x, v0.y); o.y = packh2(v0.z, v0.w);
        o.z = packh2(v1.x, v1.y); o.w = packh2(v1.z, v1.w);
        char* dst = (char*)g_w2h + ((size_t)by * 16 + tk) * 16384;
        *(uint4*)(dst + g2_off(row, ch)) = o;
    } else if (b < 16576){
        int i = (b - 16320) * 256 + threadIdx.x;   // n4 = 65536
        float4 v = x[i];
        uint2 w;
        w.x = packh2(v.x, v.y);
        w.y = packh2(v.z, v.w);
        ((uint2*)g_xh)[i] = w;
    } else {
        int i = (b - 16576) * 256 + threadIdx.x;   // n4 = 65536
        float4 v = W1[i];
        uint2 w;
        w.x = packh2(v.x, v.y);
        w.y = packh2(v.z, v.w);
        ((uint2*)g_w1h)[i] = w;
    }
}

// -------------------------------------------------------------------------
// Antisymmetrize, 64x64 tiles, float4 transfers, smem transpose.
// Diagonal tiles: load only lower-half quads, float4 fast path on stores.
// -------------------------------------------------------------------------
__global__ void __launch_bounds__(256) antisym64(float* __restrict__ out)
{
    __shared__ float s[64][65];
    const int bt = blockIdx.x;
    const int pr = blockIdx.y;
    int ti = 0;
    while ((ti + 1) * (ti + 2) / 2 <= pr) ti++;
    const int tj = pr - ti * (ti + 1) / 2;
    const int tx = threadIdx.x & 15;     // float4 column index (16 per row)
    const int ty = threadIdx.x >> 4;     // row group (16 rows per pass)
    float* base = out + (size_t)bt * (NMAT * NMAT);
    const bool diag = (ti == tj);

    // load 64x64 tile at (ti,tj), float4-coalesced.
    // Diagonal tiles only need s[ii][jj] for ii > jj: skip quads entirely
    // above the diagonal (tx*4 > r means cols > row -> unused).
    #pragma unroll
    for (int it = 0; it < 4; it++){
        int r = ty + it * 16;
        if (diag && tx * 4 > r) continue;
        float4 v = *(const float4*)(base + (size_t)(ti * 64 + r) * NMAT + tj * 64 + tx * 4);
        s[r][tx * 4 + 0] = v.x;
        s[r][tx * 4 + 1] = v.y;
        s[r][tx * 4 + 2] = v.z;
        s[r][tx * 4 + 3] = v.w;
    }
    __syncthreads();

    if (!diag){
        // write full transposed-negated tile at (tj,ti), float4-coalesced
        #pragma unroll
        for (int it = 0; it < 4; it++){
            int jj = ty + it * 16;
            float4 v;
            v.x = -s[tx * 4 + 0][jj];
            v.y = -s[tx * 4 + 1][jj];
            v.z = -s[tx * 4 + 2][jj];
            v.w = -s[tx * 4 + 3][jj];
            *(float4*)(base + (size_t)(tj * 64 + jj) * NMAT + ti * 64 + tx * 4) = v;
        }
    } else {
        // diagonal tile: upper-strict = -lower^T, diagonal = 0
        #pragma unroll
        for (int it = 0; it < 4; it++){
            int jj = ty + it * 16;
            float* orow = base + (size_t)(ti * 64 + jj) * NMAT + ti * 64;
            int ii0 = tx * 4;
            if (ii0 > jj){
                // whole quad strictly above diagonal: vector store
                float4 v;
                v.x = -s[ii0 + 0][jj];
                v.y = -s[ii0 + 1][jj];
                v.z = -s[ii0 + 2][jj];
                v.w = -s[ii0 + 3][jj];
                *(float4*)(orow + ii0) = v;
            } else if (ii0 + 3 >= jj){
                // straddles the diagonal: per-element
                #pragma unroll
                for (int k = 0; k < 4; k++){
                    int ii = ii0 + k;
                    if (ii > jj)       orow[ii] = -s[ii][jj];
                    else if (ii == jj) orow[ii] = 0.0f;
                }
            }
        }
    }
}

// -------------------------------------------------------------------------
extern "C" void kernel_launch(void* const* d_in, const int* in_sizes, int n_in,
                              void* d_out, int out_size)
{
    const float* x  = (const float*)d_in[0];   // [1024, 256]
    const float* W1 = (const float*)d_in[1];   // [1024, 256]
    const float* b1 = (const float*)d_in[2];   // [1024]
    const float* W2 = (const float*)d_in[3];   // [32896, 1024]
    const float* b2 = (const float*)d_in[4];   // [32896]
    float* out = (float*)d_out;                // [1024, 256, 256]

    cudaFuncSetAttribute(gemm1_f16, cudaFuncAttributeMaxDynamicSharedMemorySize, G1_SMEM);
    cudaFuncSetAttribute(gemm2_f16, cudaFuncAttributeMaxDynamicSharedMemorySize, G2_SMEM);

    // All conversions in ONE launch (W2 tiled+swizzled, x/W1 row-major)
    conv_all<<<16832, 256>>>(W2, (const float4*)x, (const float4*)W1);

    // GEMM1: h = softplus(x @ W1^T + b1) -> g_h (fp16, tiled)   (M=1024, N=1024, K=256)
    gemm1_f16<<<dim3(8, 8), 256, G1_SMEM>>>(b1);
    // GEMM2: elements = h @ W2^T + b2 -> strict lower triangle of out
    //        (M=1024, N=TRI=255*128, K=1024), bulk-copy pipeline, 64x64 warp tiles
    gemm2_f16<<<dim3(8, 255), 128, G2_SMEM>>>(b2, out);
    // Upper triangle = -lower^T, diagonal = 0 (64x64 float4 tiles)
    antisym64<<<dim3(1024, 10), 256>>>(out);
}